// round 13
// baseline (speedup 1.0000x reference)
#include <cuda_runtime.h>
#include <cuda_fp16.h>
#include <cstdint>
#include <cstddef>

#define S_SIZE 4096
#define IN_SZ  2048
#define KTOT   6144
#define BATCH  4096

// ---------------- scratch (device globals; no allocation APIs) ----------------
__device__ __half g_W[4ull * S_SIZE * KTOT];            // [gate][s][k] fp16 K-major (M-stacked)
__device__ __half g_Zt[(size_t)BATCH * KTOT];           // [b][k] fp16 K-major
__device__ __half g_Z[4ull * S_SIZE * BATCH];           // preactivations fp16

// ---------------- helpers ----------------
__device__ __forceinline__ uint32_t smem_u32(const void* p) {
    return (uint32_t)__cvta_generic_to_shared(p);
}

__device__ __forceinline__ void ldsm_x4(uint32_t& r0, uint32_t& r1, uint32_t& r2, uint32_t& r3,
                                        uint32_t addr) {
    asm volatile("ldmatrix.sync.aligned.m8n8.x4.shared.b16 {%0,%1,%2,%3}, [%4];"
                 : "=r"(r0), "=r"(r1), "=r"(r2), "=r"(r3) : "r"(addr));
}

__device__ __forceinline__ void mma16816(float* d, const uint32_t* a, const uint32_t* b) {
    asm volatile(
        "mma.sync.aligned.m16n8k16.row.col.f32.f16.f16.f32 "
        "{%0,%1,%2,%3}, {%4,%5,%6,%7}, {%8,%9}, {%0,%1,%2,%3};"
        : "+f"(d[0]), "+f"(d[1]), "+f"(d[2]), "+f"(d[3])
        : "r"(a[0]), "r"(a[1]), "r"(a[2]), "r"(a[3]), "r"(b[0]), "r"(b[1]));
}

__device__ __forceinline__ float sigf(float x) { return 1.0f / (1.0f + __expf(-x)); }
__device__ __forceinline__ float tanh_(float x) { return 2.0f * sigf(2.0f * x) - 1.0f; }

__device__ __forceinline__ uint4 pack8(float4 v0, float4 v1) {
    __half2 h0 = __floats2half2_rn(v0.x, v0.y);
    __half2 h1 = __floats2half2_rn(v0.z, v0.w);
    __half2 h2 = __floats2half2_rn(v1.x, v1.y);
    __half2 h3 = __floats2half2_rn(v1.z, v1.w);
    uint4 p;
    p.x = *(uint32_t*)&h0; p.y = *(uint32_t*)&h1;
    p.z = *(uint32_t*)&h2; p.w = *(uint32_t*)&h3;
    return p;
}

// ---------------- fused convert: 3 grid segments ----------------
// seg0 [0, NB_WIN):            pack W_in halves (4 gates x 4096 x 2048), 2^22 chunks of 8
// seg1 [NB_WIN, NB_WIN+NB_WH): pack W_h halves  (4 gates x 4096 x 4096), 2^23 chunks of 8
// seg2 rest:                   activation transpose
#define NB_WIN 2048
#define NB_WH  4096
#define ACT_KB (KTOT / 32)               // 192
#define NB_ACT (ACT_KB * (BATCH / 32))   // 24576

__global__ void convert_fused(const float* __restrict__ wf_in, const float* __restrict__ wf_h,
                              const float* __restrict__ wi_in, const float* __restrict__ wi_h,
                              const float* __restrict__ wc_in, const float* __restrict__ wc_h,
                              const float* __restrict__ wo_in, const float* __restrict__ wo_h,
                              const float* __restrict__ x, const float* __restrict__ h) {
    if (blockIdx.x < NB_WIN) {
        // ---- W_in pack: 2^22 chunks, 2^19 threads, 8 chunks/thread (2 batches of 4) ----
        const int tt = blockIdx.x * 256 + threadIdx.x;      // 0 .. 2^19-1
        const int stride = NB_WIN * 256;                     // 2^19
#pragma unroll
        for (int bt = 0; bt < 2; bt++) {
            float4 v[4][2];
#pragma unroll
            for (int u = 0; u < 4; u++) {
                int c = (bt * 4 + u) * stride + tt;
                int g = c >> 20;
                int rem = c & 0xFFFFF;
                int s = rem >> 8;
                int kc = rem & 255;
                const float* win = (g == 0) ? wf_in : (g == 1) ? wi_in
                                 : (g == 2) ? wc_in : wo_in;
                const float* p = win + ((size_t)s << 11) + kc * 8;
                v[u][0] = *(const float4*)p;
                v[u][1] = *(const float4*)(p + 4);
            }
#pragma unroll
            for (int u = 0; u < 4; u++) {
                int c = (bt * 4 + u) * stride + tt;
                int g = c >> 20;
                int rem = c & 0xFFFFF;
                int s = rem >> 8;
                int kc = rem & 255;
                *(uint4*)(g_W + (size_t)g * ((size_t)S_SIZE * KTOT)
                              + (size_t)s * KTOT + kc * 8) = pack8(v[u][0], v[u][1]);
            }
        }
    } else if (blockIdx.x < NB_WIN + NB_WH) {
        // ---- W_h pack: 2^23 chunks, 2^20 threads, 8 chunks/thread ----
        const int tt = (blockIdx.x - NB_WIN) * 256 + threadIdx.x;   // 0 .. 2^20-1
        const int stride = NB_WH * 256;                              // 2^20
#pragma unroll
        for (int bt = 0; bt < 2; bt++) {
            float4 v[4][2];
#pragma unroll
            for (int u = 0; u < 4; u++) {
                int c = (bt * 4 + u) * stride + tt;
                int g = c >> 21;
                int rem = c & 0x1FFFFF;
                int s = rem >> 9;
                int kc = rem & 511;
                const float* wh = (g == 0) ? wf_h : (g == 1) ? wi_h
                                : (g == 2) ? wc_h : wo_h;
                const float* p = wh + ((size_t)s << 12) + kc * 8;
                v[u][0] = *(const float4*)p;
                v[u][1] = *(const float4*)(p + 4);
            }
#pragma unroll
            for (int u = 0; u < 4; u++) {
                int c = (bt * 4 + u) * stride + tt;
                int g = c >> 21;
                int rem = c & 0x1FFFFF;
                int s = rem >> 9;
                int kc = rem & 511;
                *(uint4*)(g_W + (size_t)g * ((size_t)S_SIZE * KTOT)
                              + (size_t)s * KTOT + IN_SZ + kc * 8) = pack8(v[u][0], v[u][1]);
            }
        }
    } else {
        // ---- activation transpose ----
        __shared__ float tile[32][33];
        const int bid = blockIdx.x - NB_WIN - NB_WH;
        const int kb = (bid % ACT_KB) * 32;
        const int bb = (bid / ACT_KB) * 32;
        const int tx = threadIdx.x & 31;
        const int ty = threadIdx.x >> 5;            // 0..7
#pragma unroll
        for (int i = 0; i < 4; i++) {
            int k = kb + ty + i * 8;
            const float* src = (k < IN_SZ) ? (x + (size_t)k * BATCH)
                                           : (h + (size_t)(k - IN_SZ) * BATCH);
            tile[ty + i * 8][tx] = src[bb + tx];
        }
        __syncthreads();
#pragma unroll
        for (int i = 0; i < 4; i++) {
            int b = bb + ty + i * 8;
            int k = kb + tx;
            g_Zt[(size_t)b * KTOT + k] = __float2half_rn(tile[tx][ty + i * 8]);
        }
    }
}

// ---------------- GEMM: Z[16384, 4096] = g_W[16384, 6144] @ g_Zt[4096, 6144]^T ----------------
// CTA 128x128, 128 threads, 4 warps 2(m) x 2(n), warp tile 64x64. Occupancy 2.
#define KBLK        64
#define NUM_IT      (KTOT / KBLK)        // 96
#define STAGE_BYTES 32768                // A 128x64 fp16 (16KB) + B 128x64 fp16 (16KB)
#define NSTAGE      3
#define SMEM_TOTAL  (NSTAGE * STAGE_BYTES)

// 2048 x 16B chunks per stage, 128 threads -> 16 each
__device__ __forceinline__ void fill_stage(uint32_t sbase, const __half* Ag, const __half* Bg,
                                           int kblk, int tid) {
#pragma unroll
    for (int i = 0; i < 16; i++) {
        int id = i * 128 + tid;
        int op = id >> 10;               // 0 = A, 1 = B
        int r  = (id >> 3) & 127;
        int c  = id & 7;
        const __half* src = (op ? Bg : Ag) + (size_t)r * KTOT + kblk + c * 8;
        uint32_t dst = sbase + (uint32_t)op * 16384u + (uint32_t)r * 128u
                     + (uint32_t)((c ^ (r & 7)) * 16);
        asm volatile("cp.async.cg.shared.global [%0], [%1], 16;\n"
                     :: "r"(dst), "l"(src) : "memory");
    }
    asm volatile("cp.async.commit_group;\n" ::: "memory");
}

__global__ void __launch_bounds__(128, 2) lstm_gemm(void) {
    extern __shared__ __align__(1024) char smem[];
    const uint32_t sb0 = smem_u32(smem);
    const int tid = threadIdx.x;
    const int wid = tid >> 5, l = tid & 31;
    const int wm = wid >> 1, wn = wid & 1;          // 2x2 warps, warp tile 64x64
    const int m0 = (int)blockIdx.y * 128;           // over 16384
    const int n0 = (int)blockIdx.x * 128;           // over 4096

    const __half* Ag = g_W  + (size_t)m0 * KTOT;
    const __half* Bg = g_Zt + (size_t)n0 * KTOT;

    int arow[4], brow[4];
#pragma unroll
    for (int t = 0; t < 4; t++)
        arow[t] = wm * 64 + t * 16 + (l & 7) + ((l >> 3) & 1) * 8;
#pragma unroll
    for (int p = 0; p < 4; p++)
        brow[p] = wn * 64 + p * 16 + (l & 7) + ((l >> 4) & 1) * 8;
    const int a_sel = (l >> 4) & 1;
    const int b_sel = (l >> 3) & 1;

    float acc[4][8][4];
#pragma unroll
    for (int t = 0; t < 4; t++)
#pragma unroll
        for (int p = 0; p < 8; p++)
#pragma unroll
            for (int q = 0; q < 4; q++) acc[t][p][q] = 0.0f;

    fill_stage(sb0, Ag, Bg, 0, tid);
    fill_stage(sb0 + STAGE_BYTES, Ag, Bg, KBLK, tid);

    for (int it = 0; it < NUM_IT; it++) {
        if (it == NUM_IT - 1) asm volatile("cp.async.wait_group 0;\n" ::: "memory");
        else                  asm volatile("cp.async.wait_group 1;\n" ::: "memory");
        __syncthreads();
        // fill(it+2) targets stage (it-1)%3, whose reads finished before the sync above.
        if (it + 2 < NUM_IT)
            fill_stage(sb0 + (uint32_t)((it + 2) % NSTAGE) * STAGE_BYTES,
                       Ag, Bg, (it + 2) * KBLK, tid);
        const uint32_t sa = sb0 + (uint32_t)(it % NSTAGE) * STAGE_BYTES;
        const uint32_t sbq = sa + 16384u;
#pragma unroll
        for (int ks = 0; ks < 4; ks++) {
            uint32_t a[4][4], b[4][4];
#pragma unroll
            for (int t = 0; t < 4; t++) {
                uint32_t addr = sa + (uint32_t)arow[t] * 128u
                              + (uint32_t)(((ks * 2 + a_sel) ^ (arow[t] & 7)) * 16);
                ldsm_x4(a[t][0], a[t][1], a[t][2], a[t][3], addr);
            }
#pragma unroll
            for (int p = 0; p < 4; p++) {
                uint32_t addr = sbq + (uint32_t)brow[p] * 128u
                              + (uint32_t)(((ks * 2 + b_sel) ^ (brow[p] & 7)) * 16);
                ldsm_x4(b[p][0], b[p][1], b[p][2], b[p][3], addr);
            }
#pragma unroll
            for (int t = 0; t < 4; t++)
#pragma unroll
                for (int p = 0; p < 8; p++)
                    mma16816(acc[t][p], a[t], &b[p >> 1][(p & 1) * 2]);
        }
    }

    // epilogue: write fp16 preactivations to g_Z
    const int g  = l >> 2;
    const int tg = l & 3;
#pragma unroll
    for (int t = 0; t < 4; t++) {
#pragma unroll
        for (int p = 0; p < 8; p++) {
            int row = m0 + wm * 64 + t * 16 + g;
            int col = n0 + wn * 64 + p * 8 + tg * 2;
            __half2* z0 = (__half2*)(g_Z + (size_t)row * BATCH + col);
            z0[0] = __floats2half2_rn(acc[t][p][0], acc[t][p][1]);
            __half2* z1 = (__half2*)(g_Z + (size_t)(row + 8) * BATCH + col);
            z1[0] = __floats2half2_rn(acc[t][p][2], acc[t][p][3]);
        }
    }
}

// ---------------- elementwise combine: 8 elems/thread ----------------
__global__ void lstm_elem(const float* __restrict__ prev_state,
                          const float* __restrict__ bf, const float* __restrict__ bi,
                          const float* __restrict__ bc, const float* __restrict__ bo,
                          float* __restrict__ out) {
    const size_t SB = (size_t)S_SIZE * BATCH;
    size_t i = (size_t)blockIdx.x * blockDim.x + threadIdx.x;
    size_t e = i * 8;
    if (e >= SB) return;
    int m = (int)(e >> 12);                 // BATCH = 4096; 8-groups never cross rows
    const float vbf = bf[m], vbi = bi[m], vbc = bc[m], vbo = bo[m];

    uint4 rf = *(const uint4*)(g_Z + e);
    uint4 ri = *(const uint4*)(g_Z + SB + e);
    uint4 rc = *(const uint4*)(g_Z + 2 * SB + e);
    uint4 ro = *(const uint4*)(g_Z + 3 * SB + e);
    float4 cp0 = *(const float4*)(prev_state + e);
    float4 cp1 = *(const float4*)(prev_state + e + 4);

    float zfv[8], ziv[8], zcv[8], zov[8], cpv[8], nsv[8], ov[8];
    const uint32_t* rfp = &rf.x; const uint32_t* rip = &ri.x;
    const uint32_t* rcp = &rc.x; const uint32_t* rop = &ro.x;
#pragma unroll
    for (int q = 0; q < 4; q++) {
        float2 f2;
        f2 = __half22float2(*(const __half2*)&rfp[q]); zfv[2*q] = f2.x; zfv[2*q+1] = f2.y;
        f2 = __half22float2(*(const __half2*)&rip[q]); ziv[2*q] = f2.x; ziv[2*q+1] = f2.y;
        f2 = __half22float2(*(const __half2*)&rcp[q]); zcv[2*q] = f2.x; zcv[2*q+1] = f2.y;
        f2 = __half22float2(*(const __half2*)&rop[q]); zov[2*q] = f2.x; zov[2*q+1] = f2.y;
    }
    cpv[0] = cp0.x; cpv[1] = cp0.y; cpv[2] = cp0.z; cpv[3] = cp0.w;
    cpv[4] = cp1.x; cpv[5] = cp1.y; cpv[6] = cp1.z; cpv[7] = cp1.w;
#pragma unroll
    for (int q = 0; q < 8; q++) {
        float f  = sigf(zfv[q] + vbf);
        float ig = sigf(ziv[q] + vbi);
        float ct = tanh_(zcv[q] + vbc);
        float og = sigf(zov[q] + vbo);
        float ns = cpv[q] * f + ig * ct;
        nsv[q] = ns;
        ov[q]  = tanh_(ns) * og;
    }
    *(float4*)(out + e)          = make_float4(nsv[0], nsv[1], nsv[2], nsv[3]);
    *(float4*)(out + e + 4)      = make_float4(nsv[4], nsv[5], nsv[6], nsv[7]);
    *(float4*)(out + SB + e)     = make_float4(ov[0], ov[1], ov[2], ov[3]);
    *(float4*)(out + SB + e + 4) = make_float4(ov[4], ov[5], ov[6], ov[7]);
}

// ---------------- host ----------------
extern "C" void kernel_launch(void* const* d_in, const int* in_sizes, int n_in,
                              void* d_out, int out_size) {
    const float* input      = (const float*)d_in[0];
    const float* prev_out   = (const float*)d_in[1];
    const float* prev_state = (const float*)d_in[2];
    const float* W_in_f = (const float*)d_in[3];
    const float* W_h_f  = (const float*)d_in[4];
    const float* b_f    = (const float*)d_in[5];
    const float* W_in_i = (const float*)d_in[6];
    const float* W_h_i  = (const float*)d_in[7];
    const float* b_i    = (const float*)d_in[8];
    const float* W_C_i  = (const float*)d_in[9];
    const float* W_C_h  = (const float*)d_in[10];
    const float* b_C    = (const float*)d_in[11];
    const float* W_in_o = (const float*)d_in[12];
    const float* W_h_o  = (const float*)d_in[13];
    const float* b_o    = (const float*)d_in[14];

    static bool attr_set = false;
    if (!attr_set) {
        cudaFuncSetAttribute(lstm_gemm, cudaFuncAttributeMaxDynamicSharedMemorySize, SMEM_TOTAL);
        attr_set = true;
    }

    convert_fused<<<NB_WIN + NB_WH + NB_ACT, 256>>>(
        W_in_f, W_h_f, W_in_i, W_h_i, W_C_i, W_C_h, W_in_o, W_h_o, input, prev_out);
    lstm_gemm<<<dim3(BATCH / 128, 4 * S_SIZE / 128), 128, SMEM_TOTAL>>>();
    lstm_elem<<<(int)(((size_t)S_SIZE * BATCH / 8 + 255) / 256), 256>>>(
        prev_state, b_f, b_i, b_C, b_o, (float*)d_out);
}

// round 14
// speedup vs baseline: 1.0095x; 1.0095x over previous
#include <cuda_runtime.h>
#include <cuda_fp16.h>
#include <cstdint>
#include <cstddef>

#define S_SIZE 4096
#define IN_SZ  2048
#define KTOT   6144
#define BATCH  4096

// ---------------- scratch (device globals; no allocation APIs) ----------------
__device__ __half g_W[4ull * S_SIZE * KTOT];            // [gate][s][k] fp16 K-major (M-stacked)
__device__ __half g_Zt[(size_t)BATCH * KTOT];           // [b][k] fp16 K-major
__device__ __half g_Z[4ull * S_SIZE * BATCH];           // preactivations fp16

// ---------------- helpers ----------------
__device__ __forceinline__ uint32_t smem_u32(const void* p) {
    return (uint32_t)__cvta_generic_to_shared(p);
}

__device__ __forceinline__ void ldsm_x4(uint32_t& r0, uint32_t& r1, uint32_t& r2, uint32_t& r3,
                                        uint32_t addr) {
    asm volatile("ldmatrix.sync.aligned.m8n8.x4.shared.b16 {%0,%1,%2,%3}, [%4];"
                 : "=r"(r0), "=r"(r1), "=r"(r2), "=r"(r3) : "r"(addr));
}

__device__ __forceinline__ void mma16816(float* d, const uint32_t* a, const uint32_t* b) {
    asm volatile(
        "mma.sync.aligned.m16n8k16.row.col.f32.f16.f16.f32 "
        "{%0,%1,%2,%3}, {%4,%5,%6,%7}, {%8,%9}, {%0,%1,%2,%3};"
        : "+f"(d[0]), "+f"(d[1]), "+f"(d[2]), "+f"(d[3])
        : "r"(a[0]), "r"(a[1]), "r"(a[2]), "r"(a[3]), "r"(b[0]), "r"(b[1]));
}

__device__ __forceinline__ float tanh_fast(float x) {
    float r;
    asm("tanh.approx.f32 %0, %1;" : "=f"(r) : "f"(x));
    return r;
}
__device__ __forceinline__ float sig_fast(float x) {
    return fmaf(tanh_fast(0.5f * x), 0.5f, 0.5f);
}

// ---------------- fused convert: weights (blocks [0, NWB)) + acts (rest) ----------------
#define NWB 4096
#define ACT_KB (KTOT / 32)               // 192

__global__ void convert_fused(const float* __restrict__ wf_in, const float* __restrict__ wf_h,
                              const float* __restrict__ wi_in, const float* __restrict__ wi_h,
                              const float* __restrict__ wc_in, const float* __restrict__ wc_h,
                              const float* __restrict__ wo_in, const float* __restrict__ wo_h,
                              const float* __restrict__ x, const float* __restrict__ h) {
    if (blockIdx.x < NWB) {
        // ---- weight packing: 8 k-elems per step (2x float4 load, 1x uint4 store) ----
        const int per_gate8 = S_SIZE * (KTOT / 8);          // 3145728
        const int total8 = 4 * per_gate8;
        const int nthr = NWB * 256;
        for (int t = blockIdx.x * blockDim.x + threadIdx.x; t < total8; t += nthr) {
            int g = t / per_gate8;
            int rem = t - g * per_gate8;
            int s = rem / (KTOT / 8);                       // /768
            int k = (rem - s * (KTOT / 8)) * 8;
            const float* win = (g == 0) ? wf_in : (g == 1) ? wi_in : (g == 2) ? wc_in : wo_in;
            const float* wh  = (g == 0) ? wf_h  : (g == 1) ? wi_h  : (g == 2) ? wc_h  : wo_h;
            float4 v0, v1;
            if (k < IN_SZ) {
                const float* p = win + (size_t)s * IN_SZ + k;
                v0 = *(const float4*)p;
                v1 = *(const float4*)(p + 4);
            } else {
                const float* p = wh + (size_t)s * S_SIZE + (k - IN_SZ);
                v0 = *(const float4*)p;
                v1 = *(const float4*)(p + 4);
            }
            __half2 h0 = __floats2half2_rn(v0.x, v0.y);
            __half2 h1 = __floats2half2_rn(v0.z, v0.w);
            __half2 h2 = __floats2half2_rn(v1.x, v1.y);
            __half2 h3 = __floats2half2_rn(v1.z, v1.w);
            uint4 pack;
            pack.x = *(uint32_t*)&h0; pack.y = *(uint32_t*)&h1;
            pack.z = *(uint32_t*)&h2; pack.w = *(uint32_t*)&h3;
            *(uint4*)(g_W + (size_t)g * ((size_t)S_SIZE * KTOT) + (size_t)s * KTOT + k) = pack;
        }
    } else {
        // ---- activation transpose ----
        __shared__ float tile[32][33];
        const int bid = blockIdx.x - NWB;
        const int kb = (bid % ACT_KB) * 32;
        const int bb = (bid / ACT_KB) * 32;
        const int tx = threadIdx.x & 31;
        const int ty = threadIdx.x >> 5;            // 0..7
#pragma unroll
        for (int i = 0; i < 4; i++) {
            int k = kb + ty + i * 8;
            const float* src = (k < IN_SZ) ? (x + (size_t)k * BATCH)
                                           : (h + (size_t)(k - IN_SZ) * BATCH);
            tile[ty + i * 8][tx] = src[bb + tx];
        }
        __syncthreads();
#pragma unroll
        for (int i = 0; i < 4; i++) {
            int b = bb + ty + i * 8;
            int k = kb + tx;
            g_Zt[(size_t)b * KTOT + k] = __float2half_rn(tile[tx][ty + i * 8]);
        }
    }
}

// ---------------- GEMM: Z[16384, 4096] = g_W[16384, 6144] @ g_Zt[4096, 6144]^T ----------------
// CTA 128x128, 128 threads, 4 warps 2(m) x 2(n), warp tile 64x64. Occupancy 2.
#define KBLK        64
#define NUM_IT      (KTOT / KBLK)        // 96
#define STAGE_BYTES 32768                // A 128x64 fp16 (16KB) + B 128x64 fp16 (16KB)
#define NSTAGE      3
#define SMEM_TOTAL  (NSTAGE * STAGE_BYTES)

// 2048 x 16B chunks per stage, 128 threads -> 16 each
__device__ __forceinline__ void fill_stage(uint32_t sbase, const __half* Ag, const __half* Bg,
                                           int kblk, int tid) {
#pragma unroll
    for (int i = 0; i < 16; i++) {
        int id = i * 128 + tid;
        int op = id >> 10;               // 0 = A, 1 = B
        int r  = (id >> 3) & 127;
        int c  = id & 7;
        const __half* src = (op ? Bg : Ag) + (size_t)r * KTOT + kblk + c * 8;
        uint32_t dst = sbase + (uint32_t)op * 16384u + (uint32_t)r * 128u
                     + (uint32_t)((c ^ (r & 7)) * 16);
        asm volatile("cp.async.cg.shared.global [%0], [%1], 16;\n"
                     :: "r"(dst), "l"(src) : "memory");
    }
    asm volatile("cp.async.commit_group;\n" ::: "memory");
}

__global__ void __launch_bounds__(128, 2) lstm_gemm(void) {
    extern __shared__ __align__(1024) char smem[];
    const uint32_t sb0 = smem_u32(smem);
    const int tid = threadIdx.x;
    const int wid = tid >> 5, l = tid & 31;
    const int wm = wid >> 1, wn = wid & 1;          // 2x2 warps, warp tile 64x64
    const int m0 = (int)blockIdx.y * 128;           // over 16384
    const int n0 = (int)blockIdx.x * 128;           // over 4096

    const __half* Ag = g_W  + (size_t)m0 * KTOT;
    const __half* Bg = g_Zt + (size_t)n0 * KTOT;

    int arow[4], brow[4];
#pragma unroll
    for (int t = 0; t < 4; t++)
        arow[t] = wm * 64 + t * 16 + (l & 7) + ((l >> 3) & 1) * 8;
#pragma unroll
    for (int p = 0; p < 4; p++)
        brow[p] = wn * 64 + p * 16 + (l & 7) + ((l >> 4) & 1) * 8;
    const int a_sel = (l >> 4) & 1;
    const int b_sel = (l >> 3) & 1;

    float acc[4][8][4];
#pragma unroll
    for (int t = 0; t < 4; t++)
#pragma unroll
        for (int p = 0; p < 8; p++)
#pragma unroll
            for (int q = 0; q < 4; q++) acc[t][p][q] = 0.0f;

    fill_stage(sb0, Ag, Bg, 0, tid);
    fill_stage(sb0 + STAGE_BYTES, Ag, Bg, KBLK, tid);

    for (int it = 0; it < NUM_IT; it++) {
        if (it == NUM_IT - 1) asm volatile("cp.async.wait_group 0;\n" ::: "memory");
        else                  asm volatile("cp.async.wait_group 1;\n" ::: "memory");
        __syncthreads();
        // fill(it+2) targets stage (it-1)%3, whose reads finished before the sync above.
        if (it + 2 < NUM_IT)
            fill_stage(sb0 + (uint32_t)((it + 2) % NSTAGE) * STAGE_BYTES,
                       Ag, Bg, (it + 2) * KBLK, tid);
        const uint32_t sa = sb0 + (uint32_t)(it % NSTAGE) * STAGE_BYTES;
        const uint32_t sbq = sa + 16384u;
#pragma unroll
        for (int ks = 0; ks < 4; ks++) {
            uint32_t a[4][4], b[4][4];
#pragma unroll
            for (int t = 0; t < 4; t++) {
                uint32_t addr = sa + (uint32_t)arow[t] * 128u
                              + (uint32_t)(((ks * 2 + a_sel) ^ (arow[t] & 7)) * 16);
                ldsm_x4(a[t][0], a[t][1], a[t][2], a[t][3], addr);
            }
#pragma unroll
            for (int p = 0; p < 4; p++) {
                uint32_t addr = sbq + (uint32_t)brow[p] * 128u
                              + (uint32_t)(((ks * 2 + b_sel) ^ (brow[p] & 7)) * 16);
                ldsm_x4(b[p][0], b[p][1], b[p][2], b[p][3], addr);
            }
#pragma unroll
            for (int t = 0; t < 4; t++)
#pragma unroll
                for (int p = 0; p < 8; p++)
                    mma16816(acc[t][p], a[t], &b[p >> 1][(p & 1) * 2]);
        }
    }

    // epilogue: write fp16 preactivations to g_Z
    const int g  = l >> 2;
    const int tg = l & 3;
#pragma unroll
    for (int t = 0; t < 4; t++) {
#pragma unroll
        for (int p = 0; p < 8; p++) {
            int row = m0 + wm * 64 + t * 16 + g;
            int col = n0 + wn * 64 + p * 8 + tg * 2;
            __half2* z0 = (__half2*)(g_Z + (size_t)row * BATCH + col);
            z0[0] = __floats2half2_rn(acc[t][p][0], acc[t][p][1]);
            __half2* z1 = (__half2*)(g_Z + (size_t)(row + 8) * BATCH + col);
            z1[0] = __floats2half2_rn(acc[t][p][2], acc[t][p][3]);
        }
    }
}

// ---------------- elementwise combine: 8 elems/thread, tanh.approx activations ----------------
__global__ void lstm_elem(const float* __restrict__ prev_state,
                          const float* __restrict__ bf, const float* __restrict__ bi,
                          const float* __restrict__ bc, const float* __restrict__ bo,
                          float* __restrict__ out) {
    const size_t SB = (size_t)S_SIZE * BATCH;
    size_t i = (size_t)blockIdx.x * blockDim.x + threadIdx.x;
    size_t e = i * 8;
    if (e >= SB) return;
    int m = (int)(e >> 12);                 // BATCH = 4096; 8-groups never cross rows
    const float vbf = bf[m], vbi = bi[m], vbc = bc[m], vbo = bo[m];

    uint4 rf = *(const uint4*)(g_Z + e);
    uint4 ri = *(const uint4*)(g_Z + SB + e);
    uint4 rc = *(const uint4*)(g_Z + 2 * SB + e);
    uint4 ro = *(const uint4*)(g_Z + 3 * SB + e);
    float4 cp0 = *(const float4*)(prev_state + e);
    float4 cp1 = *(const float4*)(prev_state + e + 4);

    float zfv[8], ziv[8], zcv[8], zov[8], cpv[8], nsv[8], ov[8];
    const uint32_t* rfp = &rf.x; const uint32_t* rip = &ri.x;
    const uint32_t* rcp = &rc.x; const uint32_t* rop = &ro.x;
#pragma unroll
    for (int q = 0; q < 4; q++) {
        float2 f2;
        f2 = __half22float2(*(const __half2*)&rfp[q]); zfv[2*q] = f2.x; zfv[2*q+1] = f2.y;
        f2 = __half22float2(*(const __half2*)&rip[q]); ziv[2*q] = f2.x; ziv[2*q+1] = f2.y;
        f2 = __half22float2(*(const __half2*)&rcp[q]); zcv[2*q] = f2.x; zcv[2*q+1] = f2.y;
        f2 = __half22float2(*(const __half2*)&rop[q]); zov[2*q] = f2.x; zov[2*q+1] = f2.y;
    }
    cpv[0] = cp0.x; cpv[1] = cp0.y; cpv[2] = cp0.z; cpv[3] = cp0.w;
    cpv[4] = cp1.x; cpv[5] = cp1.y; cpv[6] = cp1.z; cpv[7] = cp1.w;
#pragma unroll
    for (int q = 0; q < 8; q++) {
        float f  = sig_fast(zfv[q] + vbf);
        float ig = sig_fast(ziv[q] + vbi);
        float ct = tanh_fast(zcv[q] + vbc);
        float og = sig_fast(zov[q] + vbo);
        float ns = fmaf(cpv[q], f, ig * ct);
        nsv[q] = ns;
        ov[q]  = tanh_fast(ns) * og;
    }
    *(float4*)(out + e)          = make_float4(nsv[0], nsv[1], nsv[2], nsv[3]);
    *(float4*)(out + e + 4)      = make_float4(nsv[4], nsv[5], nsv[6], nsv[7]);
    *(float4*)(out + SB + e)     = make_float4(ov[0], ov[1], ov[2], ov[3]);
    *(float4*)(out + SB + e + 4) = make_float4(ov[4], ov[5], ov[6], ov[7]);
}

// ---------------- host ----------------
extern "C" void kernel_launch(void* const* d_in, const int* in_sizes, int n_in,
                              void* d_out, int out_size) {
    const float* input      = (const float*)d_in[0];
    const float* prev_out   = (const float*)d_in[1];
    const float* prev_state = (const float*)d_in[2];
    const float* W_in_f = (const float*)d_in[3];
    const float* W_h_f  = (const float*)d_in[4];
    const float* b_f    = (const float*)d_in[5];
    const float* W_in_i = (const float*)d_in[6];
    const float* W_h_i  = (const float*)d_in[7];
    const float* b_i    = (const float*)d_in[8];
    const float* W_C_i  = (const float*)d_in[9];
    const float* W_C_h  = (const float*)d_in[10];
    const float* b_C    = (const float*)d_in[11];
    const float* W_in_o = (const float*)d_in[12];
    const float* W_h_o  = (const float*)d_in[13];
    const float* b_o    = (const float*)d_in[14];

    static bool attr_set = false;
    if (!attr_set) {
        cudaFuncSetAttribute(lstm_gemm, cudaFuncAttributeMaxDynamicSharedMemorySize, SMEM_TOTAL);
        attr_set = true;
    }

    convert_fused<<<NWB + ACT_KB * (BATCH / 32), 256>>>(
        W_in_f, W_h_f, W_in_i, W_h_i, W_C_i, W_C_h, W_in_o, W_h_o, input, prev_out);
    lstm_gemm<<<dim3(BATCH / 128, 4 * S_SIZE / 128), 128, SMEM_TOTAL>>>();
    lstm_elem<<<(int)(((size_t)S_SIZE * BATCH / 8 + 255) / 256), 256>>>(
        prev_state, b_f, b_i, b_C, b_o, (float*)d_out);
}

// round 15
// speedup vs baseline: 1.0340x; 1.0243x over previous
#include <cuda_runtime.h>
#include <cuda_fp16.h>
#include <cstdint>
#include <cstddef>

#define S_SIZE 4096
#define IN_SZ  2048
#define KTOT   6144
#define BATCH  4096

// ---------------- scratch (device globals; no allocation APIs) ----------------
// g_W rows interleaved: row = (s>>5)*128 + gate*32 + (s&31)
__device__ __half g_W[4ull * S_SIZE * KTOT];
__device__ __half g_Zt[(size_t)BATCH * KTOT];           // [b][k] fp16 K-major

// ---------------- helpers ----------------
__device__ __forceinline__ uint32_t smem_u32(const void* p) {
    return (uint32_t)__cvta_generic_to_shared(p);
}

__device__ __forceinline__ void ldsm_x4(uint32_t& r0, uint32_t& r1, uint32_t& r2, uint32_t& r3,
                                        uint32_t addr) {
    asm volatile("ldmatrix.sync.aligned.m8n8.x4.shared.b16 {%0,%1,%2,%3}, [%4];"
                 : "=r"(r0), "=r"(r1), "=r"(r2), "=r"(r3) : "r"(addr));
}

__device__ __forceinline__ void mma16816(float* d, const uint32_t* a, const uint32_t* b) {
    asm volatile(
        "mma.sync.aligned.m16n8k16.row.col.f32.f16.f16.f32 "
        "{%0,%1,%2,%3}, {%4,%5,%6,%7}, {%8,%9}, {%0,%1,%2,%3};"
        : "+f"(d[0]), "+f"(d[1]), "+f"(d[2]), "+f"(d[3])
        : "r"(a[0]), "r"(a[1]), "r"(a[2]), "r"(a[3]), "r"(b[0]), "r"(b[1]));
}

__device__ __forceinline__ float tanh_fast(float x) {
    float r;
    asm("tanh.approx.f32 %0, %1;" : "=f"(r) : "f"(x));
    return r;
}
__device__ __forceinline__ float sig_fast(float x) {
    return fmaf(tanh_fast(0.5f * x), 0.5f, 0.5f);
}

// ---------------- fused convert: weights (blocks [0, NWB)) + acts (rest) ----------------
#define NWB 4096
#define ACT_KB (KTOT / 32)               // 192

__global__ void convert_fused(const float* __restrict__ wf_in, const float* __restrict__ wf_h,
                              const float* __restrict__ wi_in, const float* __restrict__ wi_h,
                              const float* __restrict__ wc_in, const float* __restrict__ wc_h,
                              const float* __restrict__ wo_in, const float* __restrict__ wo_h,
                              const float* __restrict__ x, const float* __restrict__ h) {
    if (blockIdx.x < NWB) {
        // ---- weight packing: 8 k-elems per step, gate-interleaved destination rows ----
        const int per_gate8 = S_SIZE * (KTOT / 8);          // 3145728
        const int total8 = 4 * per_gate8;
        const int nthr = NWB * 256;
        for (int t = blockIdx.x * blockDim.x + threadIdx.x; t < total8; t += nthr) {
            int g = t / per_gate8;
            int rem = t - g * per_gate8;
            int s = rem / (KTOT / 8);                       // /768
            int k = (rem - s * (KTOT / 8)) * 8;
            const float* win = (g == 0) ? wf_in : (g == 1) ? wi_in : (g == 2) ? wc_in : wo_in;
            const float* wh  = (g == 0) ? wf_h  : (g == 1) ? wi_h  : (g == 2) ? wc_h  : wo_h;
            float4 v0, v1;
            if (k < IN_SZ) {
                const float* p = win + (size_t)s * IN_SZ + k;
                v0 = *(const float4*)p;
                v1 = *(const float4*)(p + 4);
            } else {
                const float* p = wh + (size_t)s * S_SIZE + (k - IN_SZ);
                v0 = *(const float4*)p;
                v1 = *(const float4*)(p + 4);
            }
            __half2 h0 = __floats2half2_rn(v0.x, v0.y);
            __half2 h1 = __floats2half2_rn(v0.z, v0.w);
            __half2 h2 = __floats2half2_rn(v1.x, v1.y);
            __half2 h3 = __floats2half2_rn(v1.z, v1.w);
            uint4 pack;
            pack.x = *(uint32_t*)&h0; pack.y = *(uint32_t*)&h1;
            pack.z = *(uint32_t*)&h2; pack.w = *(uint32_t*)&h3;
            int row = ((s >> 5) << 7) + (g << 5) + (s & 31);    // gate-interleaved
            *(uint4*)(g_W + (size_t)row * KTOT + k) = pack;
        }
    } else {
        // ---- activation transpose ----
        __shared__ float tile[32][33];
        const int bid = blockIdx.x - NWB;
        const int kb = (bid % ACT_KB) * 32;
        const int bb = (bid / ACT_KB) * 32;
        const int tx = threadIdx.x & 31;
        const int ty = threadIdx.x >> 5;            // 0..7
#pragma unroll
        for (int i = 0; i < 4; i++) {
            int k = kb + ty + i * 8;
            const float* src = (k < IN_SZ) ? (x + (size_t)k * BATCH)
                                           : (h + (size_t)(k - IN_SZ) * BATCH);
            tile[ty + i * 8][tx] = src[bb + tx];
        }
        __syncthreads();
#pragma unroll
        for (int i = 0; i < 4; i++) {
            int b = bb + ty + i * 8;
            int k = kb + tx;
            g_Zt[(size_t)b * KTOT + k] = __float2half_rn(tile[tx][ty + i * 8]);
        }
    }
}

// ---------------- GEMM + fused LSTM epilogue ----------------
// CTA 128x128, 128 threads, 4 warps 2(m) x 2(n), warp tile 64x64, occupancy 2.
// One CTA = all 4 gates of a 32(state-rows) x 128(batch) patch.
#define KBLK        64
#define NUM_IT      (KTOT / KBLK)        // 96
#define STAGE_BYTES 32768
#define NSTAGE      3
#define SMEM_TOTAL  (NSTAGE * STAGE_BYTES)
#define EPI_STRIDE  136                  // fp16 units; 34 KB epi buffer, conflict-free

__device__ __forceinline__ void fill_stage(uint32_t sbase, const __half* Ag, const __half* Bg,
                                           int kblk, int tid) {
#pragma unroll
    for (int i = 0; i < 16; i++) {
        int id = i * 128 + tid;
        int op = id >> 10;               // 0 = A, 1 = B
        int r  = (id >> 3) & 127;
        int c  = id & 7;
        const __half* src = (op ? Bg : Ag) + (size_t)r * KTOT + kblk + c * 8;
        uint32_t dst = sbase + (uint32_t)op * 16384u + (uint32_t)r * 128u
                     + (uint32_t)((c ^ (r & 7)) * 16);
        asm volatile("cp.async.cg.shared.global [%0], [%1], 16;\n"
                     :: "r"(dst), "l"(src) : "memory");
    }
    asm volatile("cp.async.commit_group;\n" ::: "memory");
}

__global__ void __launch_bounds__(128, 2) lstm_gemm(
    const float* __restrict__ prev_state,
    const float* __restrict__ bfp, const float* __restrict__ bip,
    const float* __restrict__ bcp, const float* __restrict__ bop,
    float* __restrict__ out)
{
    extern __shared__ __align__(1024) char smem[];
    const uint32_t sb0 = smem_u32(smem);
    const int tid = threadIdx.x;
    const int wid = tid >> 5, l = tid & 31;
    const int wm = wid >> 1, wn = wid & 1;          // 2x2 warps, warp tile 64x64
    const int m0 = (int)blockIdx.y * 128;           // over 16384 (interleaved rows)
    const int n0 = (int)blockIdx.x * 128;           // over 4096

    const __half* Ag = g_W  + (size_t)m0 * KTOT;
    const __half* Bg = g_Zt + (size_t)n0 * KTOT;

    int arow[4], brow[4];
#pragma unroll
    for (int t = 0; t < 4; t++)
        arow[t] = wm * 64 + t * 16 + (l & 7) + ((l >> 3) & 1) * 8;
#pragma unroll
    for (int p = 0; p < 4; p++)
        brow[p] = wn * 64 + p * 16 + (l & 7) + ((l >> 4) & 1) * 8;
    const int a_sel = (l >> 4) & 1;
    const int b_sel = (l >> 3) & 1;

    float acc[4][8][4];
#pragma unroll
    for (int t = 0; t < 4; t++)
#pragma unroll
        for (int p = 0; p < 8; p++)
#pragma unroll
            for (int q = 0; q < 4; q++) acc[t][p][q] = 0.0f;

    fill_stage(sb0, Ag, Bg, 0, tid);
    fill_stage(sb0 + STAGE_BYTES, Ag, Bg, KBLK, tid);

    for (int it = 0; it < NUM_IT; it++) {
        if (it == NUM_IT - 1) asm volatile("cp.async.wait_group 0;\n" ::: "memory");
        else                  asm volatile("cp.async.wait_group 1;\n" ::: "memory");
        __syncthreads();
        if (it + 2 < NUM_IT)
            fill_stage(sb0 + (uint32_t)((it + 2) % NSTAGE) * STAGE_BYTES,
                       Ag, Bg, (it + 2) * KBLK, tid);
        const uint32_t sa = sb0 + (uint32_t)(it % NSTAGE) * STAGE_BYTES;
        const uint32_t sbq = sa + 16384u;
#pragma unroll
        for (int ks = 0; ks < 4; ks++) {
            uint32_t a[4][4], b[4][4];
#pragma unroll
            for (int t = 0; t < 4; t++) {
                uint32_t addr = sa + (uint32_t)arow[t] * 128u
                              + (uint32_t)(((ks * 2 + a_sel) ^ (arow[t] & 7)) * 16);
                ldsm_x4(a[t][0], a[t][1], a[t][2], a[t][3], addr);
            }
#pragma unroll
            for (int p = 0; p < 4; p++) {
                uint32_t addr = sbq + (uint32_t)brow[p] * 128u
                              + (uint32_t)(((ks * 2 + b_sel) ^ (brow[p] & 7)) * 16);
                ldsm_x4(b[p][0], b[p][1], b[p][2], b[p][3], addr);
            }
#pragma unroll
            for (int t = 0; t < 4; t++)
#pragma unroll
                for (int p = 0; p < 8; p++)
                    mma16816(acc[t][p], a[t], &b[p >> 1][(p & 1) * 2]);
        }
    }

    // ---- fused epilogue: exchange gates through smem, combine, write out ----
    __syncthreads();                      // main-loop smem reads done; reuse buffers
    __half* epi = (__half*)smem;          // [128 rows][EPI_STRIDE]
    const int g  = l >> 2;
    const int tg = l & 3;
#pragma unroll
    for (int t = 0; t < 4; t++) {
#pragma unroll
        for (int p = 0; p < 8; p++) {
            int row = wm * 64 + t * 16 + g;
            int col = wn * 64 + p * 8 + tg * 2;
            *(__half2*)&epi[row * EPI_STRIDE + col] =
                __floats2half2_rn(acc[t][p][0], acc[t][p][1]);
            *(__half2*)&epi[(row + 8) * EPI_STRIDE + col] =
                __floats2half2_rn(acc[t][p][2], acc[t][p][3]);
        }
    }
    __syncthreads();

    // CTA patch: state rows sblk..sblk+31, batch cols n0..n0+127.
    // Within the 128 m-rows: gate q at rows q*32 + s_loc.
    const size_t SB = (size_t)S_SIZE * BATCH;
    const int sloc = tid >> 2;            // 0..31
    const int nb   = (tid & 3) * 32;      // 32 batch cols per thread
    const int sg   = (int)blockIdx.y * 32 + sloc;
    const float vbf = bfp[sg], vbi = bip[sg], vbc = bcp[sg], vbo = bop[sg];
    const float* ps = prev_state + (size_t)sg * BATCH + n0 + nb;
    float* o_ns = out + (size_t)sg * BATCH + n0 + nb;
    float* o_o  = out + SB + (size_t)sg * BATCH + n0 + nb;
    const __half* ef = epi + (size_t)sloc * EPI_STRIDE + nb;
    const __half* ei = ef + 32 * EPI_STRIDE;
    const __half* ec = ef + 64 * EPI_STRIDE;
    const __half* eo = ef + 96 * EPI_STRIDE;
#pragma unroll
    for (int j = 0; j < 32; j += 4) {
        float2 f01 = __half22float2(*(const __half2*)&ef[j]);
        float2 f23 = __half22float2(*(const __half2*)&ef[j + 2]);
        float2 i01 = __half22float2(*(const __half2*)&ei[j]);
        float2 i23 = __half22float2(*(const __half2*)&ei[j + 2]);
        float2 c01 = __half22float2(*(const __half2*)&ec[j]);
        float2 c23 = __half22float2(*(const __half2*)&ec[j + 2]);
        float2 o01 = __half22float2(*(const __half2*)&eo[j]);
        float2 o23 = __half22float2(*(const __half2*)&eo[j + 2]);
        float4 cp = *(const float4*)(ps + j);
        float zf[4] = {f01.x, f01.y, f23.x, f23.y};
        float zi[4] = {i01.x, i01.y, i23.x, i23.y};
        float zc[4] = {c01.x, c01.y, c23.x, c23.y};
        float zo[4] = {o01.x, o01.y, o23.x, o23.y};
        float cpv[4] = {cp.x, cp.y, cp.z, cp.w};
        float nsv[4], ov[4];
#pragma unroll
        for (int q = 0; q < 4; q++) {
            float f  = sig_fast(zf[q] + vbf);
            float ig = sig_fast(zi[q] + vbi);
            float ct = tanh_fast(zc[q] + vbc);
            float og = sig_fast(zo[q] + vbo);
            float ns = fmaf(cpv[q], f, ig * ct);
            nsv[q] = ns;
            ov[q]  = tanh_fast(ns) * og;
        }
        *(float4*)(o_ns + j) = make_float4(nsv[0], nsv[1], nsv[2], nsv[3]);
        *(float4*)(o_o  + j) = make_float4(ov[0], ov[1], ov[2], ov[3]);
    }
}

// ---------------- host ----------------
extern "C" void kernel_launch(void* const* d_in, const int* in_sizes, int n_in,
                              void* d_out, int out_size) {
    const float* input      = (const float*)d_in[0];
    const float* prev_out   = (const float*)d_in[1];
    const float* prev_state = (const float*)d_in[2];
    const float* W_in_f = (const float*)d_in[3];
    const float* W_h_f  = (const float*)d_in[4];
    const float* b_f    = (const float*)d_in[5];
    const float* W_in_i = (const float*)d_in[6];
    const float* W_h_i  = (const float*)d_in[7];
    const float* b_i    = (const float*)d_in[8];
    const float* W_C_i  = (const float*)d_in[9];
    const float* W_C_h  = (const float*)d_in[10];
    const float* b_C    = (const float*)d_in[11];
    const float* W_in_o = (const float*)d_in[12];
    const float* W_h_o  = (const float*)d_in[13];
    const float* b_o    = (const float*)d_in[14];

    static bool attr_set = false;
    if (!attr_set) {
        cudaFuncSetAttribute(lstm_gemm, cudaFuncAttributeMaxDynamicSharedMemorySize, SMEM_TOTAL);
        attr_set = true;
    }

    convert_fused<<<NWB + ACT_KB * (BATCH / 32), 256>>>(
        W_in_f, W_h_f, W_in_i, W_h_i, W_C_i, W_C_h, W_in_o, W_h_o, input, prev_out);
    lstm_gemm<<<dim3(BATCH / 128, 4 * S_SIZE / 128), 128, SMEM_TOTAL>>>(
        prev_state, b_f, b_i, b_C, b_o, (float*)d_out);
}